// round 15
// baseline (speedup 1.0000x reference)
#include <cuda_runtime.h>

#define BATCH 16384

typedef unsigned long long u64;
typedef unsigned int       u32;

// Scratch (device globals: allocation-free rule)
__device__ float  g_xT[64 * BATCH];     // x transposed [i][b]
__device__ float  g_hT[64 * BATCH];     // layer0 output transposed [o][b]
__device__ float4 g_dup0[4096 * 6];     // layer0 params, duplicated (w,w) pairs
__device__ float4 g_dup1[1024 * 6];     // layer1 params, duplicated pairs
__device__ float  g_b3s0[64];           // sum_i b3 per output o, layer0
__device__ float  g_b3s1[16];           // layer1

__device__ __forceinline__ u64 fma2(u64 a, u64 b, u64 c) {
    u64 d;
    asm("fma.rn.f32x2 %0, %1, %2, %3;" : "=l"(d) : "l"(a), "l"(b), "l"(c));
    return d;
}
__device__ __forceinline__ u64 pk(float a, float b) {
    return (u64)__float_as_uint(a) | ((u64)__float_as_uint(b) << 32);
}
__device__ __forceinline__ float flo(u64 v) { return __uint_as_float((u32)v); }
__device__ __forceinline__ float fhi(u64 v) { return __uint_as_float((u32)(v >> 32)); }
__device__ __forceinline__ u64 relu2(u64 v) {
    return pk(fmaxf(flo(v), 0.0f), fmaxf(fhi(v), 0.0f));
}

// Fused prep: blocks 0..19 param duplication (5120 subnets, 1 thread each),
// blocks 20..29 b3 column sums (80 warps), blocks 30..541 x transpose tiles
// (512 tiles of 32 batch x 64 i).
__global__ __launch_bounds__(256) void prep(
    const float* __restrict__ x,
    const float* __restrict__ l0W1, const float* __restrict__ l0b1,
    const float* __restrict__ l0W2, const float* __restrict__ l0b2,
    const float* __restrict__ l0W3, const float* __restrict__ l0b3,
    const float* __restrict__ l1W1, const float* __restrict__ l1b1,
    const float* __restrict__ l1W2, const float* __restrict__ l1b2,
    const float* __restrict__ l1W3, const float* __restrict__ l1b3)
{
    __shared__ float ts[64 * 33];
    int blk = blockIdx.x, tid = threadIdx.x;

    if (blk < 20) {
        int t = blk * 256 + tid;             // 0..5119
        bool isL0 = t < 4096;
        int n = isL0 ? t : t - 4096;
        const float* W1 = isL0 ? l0W1 : l1W1;
        const float* b1 = isL0 ? l0b1 : l1b1;
        const float* W2 = isL0 ? l0W2 : l1W2;
        const float* b2 = isL0 ? l0b2 : l1b2;
        const float* W3 = isL0 ? l0W3 : l1W3;
        float4* q = (isL0 ? g_dup0 : g_dup1) + (size_t)n * 6;
        float w1a = W1[2*n], w1b = W1[2*n+1];
        float b1a = b1[2*n], b1b = b1[2*n+1];
        float w200 = W2[4*n], w201 = W2[4*n+1], w210 = W2[4*n+2], w211 = W2[4*n+3];
        float b2a = b2[2*n], b2b = b2[2*n+1];
        float w3a = W3[2*n], w3b = W3[2*n+1];
        q[0] = make_float4(w1a, w1a, w1b, w1b);
        q[1] = make_float4(b1a, b1a, b1b, b1b);
        q[2] = make_float4(w200, w200, w201, w201);
        q[3] = make_float4(w210, w210, w211, w211);
        q[4] = make_float4(b2a, b2a, b2b, b2b);
        q[5] = make_float4(w3a, w3a, w3b, w3b);
    } else if (blk < 30) {
        int wg = (blk - 20) * 8 + (tid >> 5);   // 0..79
        int lane = tid & 31;
        bool isL0 = wg < 64;
        int o = isL0 ? wg : wg - 64;
        int OUT = isL0 ? 64 : 16;
        const float* b3 = isL0 ? l0b3 : l1b3;
        float s = b3[lane * OUT + o] + b3[(lane + 32) * OUT + o];
#pragma unroll
        for (int m = 16; m; m >>= 1) s += __shfl_xor_sync(0xffffffffu, s, m);
        if (lane == 0) (isL0 ? g_b3s0 : g_b3s1)[o] = s;
    } else {
        // Transpose a 32b x 64i tile of x into g_xT, fully vectorized.
        int B0 = (blk - 30) * 32;
        int brow = tid >> 3, i4 = tid & 7;       // 32 rows, 8 f4-cols
#pragma unroll
        for (int p = 0; p < 2; p++) {
            int c = (p * 8 + i4) * 4;
            float4 v = *(const float4*)&x[(size_t)(B0 + brow) * 64 + c];
            ts[(c + 0) * 33 + brow] = v.x;
            ts[(c + 1) * 33 + brow] = v.y;
            ts[(c + 2) * 33 + brow] = v.z;
            ts[(c + 3) * 33 + brow] = v.w;
        }
        __syncthreads();
#pragma unroll
        for (int p = 0; p < 2; p++) {
            int idx = p * 256 + tid;             // 0..511
            int i = idx >> 3, bq = (idx & 7) * 4;
            float4 w = make_float4(ts[i * 33 + bq],     ts[i * 33 + bq + 1],
                                   ts[i * 33 + bq + 2], ts[i * 33 + bq + 3]);
            *(float4*)&g_xT[(size_t)i * BATCH + B0 + bq] = w;
        }
    }
}

// One KAN layer. 256 threads = 8 warps, mapped as OCOLS o-columns x NSUB
// batch-subranges (OCOLS*NSUB == 8). Warp (ol, sub) handles column
// o = o0+ol over batch [B0 + sub*256, +256); lane owns 4 f32x2 streams at
// b, b+64, b+128, b+192 (4 x LDG.64, 8B lane stride). Params for the CTA's
// OCOLS o-columns staged once in smem (OCOLS*1.5KB per i... total
// 64*OCOLS*6 float4), read as 6 uniform LDS.128 per (i,o). MINB feeds
// __launch_bounds__ to set the reg budget / CTAs-per-SM target.
// MODE 0: g_xT -> g_hT (transposed rows). MODE 1: g_hT -> dout [b][OUT].
template <int OUT, int MODE, int OCOLS, int MINB, int UNROLL>
__global__ __launch_bounds__(256, MINB) void kan_layer(float* __restrict__ dout)
{
    __shared__ float4 sp4[64 * OCOLS * 6];

    int tid  = threadIdx.x;
    int lane = tid & 31;
    int w    = tid >> 5;
    int ol   = w & (OCOLS - 1);
    int sub  = w / OCOLS;
    int o0   = blockIdx.y * OCOLS;
    int o    = o0 + ol;
    int B0   = blockIdx.x * (256 * (8 / OCOLS)) + sub * 256;
    int b    = B0 + lane * 2;

    // Stage params: per i, subnets n = i*OUT + o0..+OCOLS-1 are OCOLS*6
    // contiguous float4 in g_dup -> flat coalesced copy.
    const float4* dup = ((MODE == 0) ? g_dup0 : g_dup1);
#pragma unroll
    for (int s = tid; s < 64 * OCOLS * 6; s += 256) {
        int i = s / (OCOLS * 6);
        int r = s - i * (OCOLS * 6);
        sp4[s] = dup[(size_t)(i * OUT + o0) * 6 + r];
    }

    float s3 = ((MODE == 0) ? g_b3s0 : g_b3s1)[o];
    __syncthreads();

    const float* src = (MODE == 0) ? g_xT : g_hT;
    const float* xr  = src + b;
    const ulonglong2* pb = ((const ulonglong2*)sp4) + ol * 6;

    u64 acc0 = pk(s3, s3), acc1 = acc0, acc2 = acc0, acc3 = acc0;

#pragma unroll UNROLL
    for (int i = 0; i < 64; i++) {
        const ulonglong2* q = pb + i * (OCOLS * 6);
        ulonglong2 p0 = q[0], p1 = q[1], p2 = q[2], p3 = q[3], p4 = q[4], p5 = q[5];
        const float* xi = xr + (size_t)i * BATCH;

        u64 xv, r1, r2, ga, gb;
        xv = *(const u64*)(xi);
        r1 = relu2(fma2(p0.x, xv, p1.x));
        r2 = relu2(fma2(p0.y, xv, p1.y));
        ga = relu2(fma2(p2.x, r1, fma2(p2.y, r2, p4.x)));
        gb = relu2(fma2(p3.x, r1, fma2(p3.y, r2, p4.y)));
        acc0 = fma2(p5.y, gb, fma2(p5.x, ga, acc0));

        xv = *(const u64*)(xi + 64);
        r1 = relu2(fma2(p0.x, xv, p1.x));
        r2 = relu2(fma2(p0.y, xv, p1.y));
        ga = relu2(fma2(p2.x, r1, fma2(p2.y, r2, p4.x)));
        gb = relu2(fma2(p3.x, r1, fma2(p3.y, r2, p4.y)));
        acc1 = fma2(p5.y, gb, fma2(p5.x, ga, acc1));

        xv = *(const u64*)(xi + 128);
        r1 = relu2(fma2(p0.x, xv, p1.x));
        r2 = relu2(fma2(p0.y, xv, p1.y));
        ga = relu2(fma2(p2.x, r1, fma2(p2.y, r2, p4.x)));
        gb = relu2(fma2(p3.x, r1, fma2(p3.y, r2, p4.y)));
        acc2 = fma2(p5.y, gb, fma2(p5.x, ga, acc2));

        xv = *(const u64*)(xi + 192);
        r1 = relu2(fma2(p0.x, xv, p1.x));
        r2 = relu2(fma2(p0.y, xv, p1.y));
        ga = relu2(fma2(p2.x, r1, fma2(p2.y, r2, p4.x)));
        gb = relu2(fma2(p3.x, r1, fma2(p3.y, r2, p4.y)));
        acc3 = fma2(p5.y, gb, fma2(p5.x, ga, acc3));
    }

    if (MODE == 0) {
        float* row = g_hT + (size_t)o * BATCH + b;
        *(u64*)(row)       = acc0;
        *(u64*)(row + 64)  = acc1;
        *(u64*)(row + 128) = acc2;
        *(u64*)(row + 192) = acc3;
    } else {
        dout[(size_t)(b + 0)   * OUT + o] = flo(acc0);
        dout[(size_t)(b + 1)   * OUT + o] = fhi(acc0);
        dout[(size_t)(b + 64)  * OUT + o] = flo(acc1);
        dout[(size_t)(b + 65)  * OUT + o] = fhi(acc1);
        dout[(size_t)(b + 128) * OUT + o] = flo(acc2);
        dout[(size_t)(b + 129) * OUT + o] = fhi(acc2);
        dout[(size_t)(b + 192) * OUT + o] = flo(acc3);
        dout[(size_t)(b + 193) * OUT + o] = fhi(acc3);
    }
}

extern "C" void kernel_launch(void* const* d_in, const int* in_sizes, int n_in,
                              void* d_out, int out_size)
{
    const float* x    = (const float*)d_in[0];
    const float* l0W1 = (const float*)d_in[1];
    const float* l0b1 = (const float*)d_in[2];
    const float* l0W2 = (const float*)d_in[3];
    const float* l0b2 = (const float*)d_in[4];
    const float* l0W3 = (const float*)d_in[5];
    const float* l0b3 = (const float*)d_in[6];
    const float* l1W1 = (const float*)d_in[7];
    const float* l1b1 = (const float*)d_in[8];
    const float* l1W2 = (const float*)d_in[9];
    const float* l1b2 = (const float*)d_in[10];
    const float* l1W3 = (const float*)d_in[11];
    const float* l1b3 = (const float*)d_in[12];
    float* out = (float*)d_out;

    prep<<<542, 256>>>(x, l0W1, l0b1, l0W2, l0b2, l0W3, l0b3,
                          l1W1, l1b1, l1W2, l1b2, l1W3, l1b3);
    // layer0: 4 o-cols x 2 subranges, 24KB smem, 5 CTAs/SM target, unroll 1
    kan_layer<64, 0, 4, 5, 1><<<dim3(BATCH / 512, 16), 256>>>(nullptr);  // 512 CTAs
    // layer1: R6 config (8 o-cols, 48KB, default regs, unroll 2)
    kan_layer<16, 1, 8, 1, 2><<<dim3(BATCH / 256, 2), 256>>>(out);       // 128 CTAs
}

// round 17
// speedup vs baseline: 1.2028x; 1.2028x over previous
#include <cuda_runtime.h>

#define BATCH 16384

typedef unsigned long long u64;
typedef unsigned int       u32;

// Scratch (device globals: allocation-free rule). One pad row each so the
// software-pipeline prefetch of row 64 stays in-bounds.
__device__ float  g_xT[65 * BATCH];     // x transposed [i][b] (+pad row)
__device__ float  g_hT[65 * BATCH];     // layer0 out transposed [o][b] (+pad)
__device__ float4 g_dup0[4096 * 6];     // layer0 params, duplicated (w,w) pairs
__device__ float4 g_dup1[1024 * 6];     // layer1 params, duplicated pairs
__device__ float  g_b3s0[64];           // sum_i b3 per output o, layer0
__device__ float  g_b3s1[16];           // layer1

__device__ __forceinline__ u64 fma2(u64 a, u64 b, u64 c) {
    u64 d;
    asm("fma.rn.f32x2 %0, %1, %2, %3;" : "=l"(d) : "l"(a), "l"(b), "l"(c));
    return d;
}
__device__ __forceinline__ u64 pk(float a, float b) {
    return (u64)__float_as_uint(a) | ((u64)__float_as_uint(b) << 32);
}
__device__ __forceinline__ float flo(u64 v) { return __uint_as_float((u32)v); }
__device__ __forceinline__ float fhi(u64 v) { return __uint_as_float((u32)(v >> 32)); }
__device__ __forceinline__ u64 relu2(u64 v) {
    return pk(fmaxf(flo(v), 0.0f), fmaxf(fhi(v), 0.0f));
}

// Fused prep: blocks 0..19 param duplication (5120 subnets, 1 thread each),
// blocks 20..29 b3 column sums (80 warps), blocks 30..541 x transpose tiles
// (512 tiles of 32 batch x 64 i).
__global__ __launch_bounds__(256) void prep(
    const float* __restrict__ x,
    const float* __restrict__ l0W1, const float* __restrict__ l0b1,
    const float* __restrict__ l0W2, const float* __restrict__ l0b2,
    const float* __restrict__ l0W3, const float* __restrict__ l0b3,
    const float* __restrict__ l1W1, const float* __restrict__ l1b1,
    const float* __restrict__ l1W2, const float* __restrict__ l1b2,
    const float* __restrict__ l1W3, const float* __restrict__ l1b3)
{
    __shared__ float ts[64 * 33];
    int blk = blockIdx.x, tid = threadIdx.x;

    if (blk < 20) {
        int t = blk * 256 + tid;             // 0..5119
        bool isL0 = t < 4096;
        int n = isL0 ? t : t - 4096;
        const float* W1 = isL0 ? l0W1 : l1W1;
        const float* b1 = isL0 ? l0b1 : l1b1;
        const float* W2 = isL0 ? l0W2 : l1W2;
        const float* b2 = isL0 ? l0b2 : l1b2;
        const float* W3 = isL0 ? l0W3 : l1W3;
        float4* q = (isL0 ? g_dup0 : g_dup1) + (size_t)n * 6;
        float w1a = W1[2*n], w1b = W1[2*n+1];
        float b1a = b1[2*n], b1b = b1[2*n+1];
        float w200 = W2[4*n], w201 = W2[4*n+1], w210 = W2[4*n+2], w211 = W2[4*n+3];
        float b2a = b2[2*n], b2b = b2[2*n+1];
        float w3a = W3[2*n], w3b = W3[2*n+1];
        q[0] = make_float4(w1a, w1a, w1b, w1b);
        q[1] = make_float4(b1a, b1a, b1b, b1b);
        q[2] = make_float4(w200, w200, w201, w201);
        q[3] = make_float4(w210, w210, w211, w211);
        q[4] = make_float4(b2a, b2a, b2b, b2b);
        q[5] = make_float4(w3a, w3a, w3b, w3b);
    } else if (blk < 30) {
        int wg = (blk - 20) * 8 + (tid >> 5);   // 0..79
        int lane = tid & 31;
        bool isL0 = wg < 64;
        int o = isL0 ? wg : wg - 64;
        int OUT = isL0 ? 64 : 16;
        const float* b3 = isL0 ? l0b3 : l1b3;
        float s = b3[lane * OUT + o] + b3[(lane + 32) * OUT + o];
#pragma unroll
        for (int m = 16; m; m >>= 1) s += __shfl_xor_sync(0xffffffffu, s, m);
        if (lane == 0) (isL0 ? g_b3s0 : g_b3s1)[o] = s;
    } else {
        // Transpose a 32b x 64i tile of x into g_xT, fully vectorized.
        int B0 = (blk - 30) * 32;
        int brow = tid >> 3, i4 = tid & 7;       // 32 rows, 8 f4-cols
#pragma unroll
        for (int p = 0; p < 2; p++) {
            int c = (p * 8 + i4) * 4;
            float4 v = *(const float4*)&x[(size_t)(B0 + brow) * 64 + c];
            ts[(c + 0) * 33 + brow] = v.x;
            ts[(c + 1) * 33 + brow] = v.y;
            ts[(c + 2) * 33 + brow] = v.z;
            ts[(c + 3) * 33 + brow] = v.w;
        }
        __syncthreads();
#pragma unroll
        for (int p = 0; p < 2; p++) {
            int idx = p * 256 + tid;             // 0..511
            int i = idx >> 3, bq = (idx & 7) * 4;
            float4 w = make_float4(ts[i * 33 + bq],     ts[i * 33 + bq + 1],
                                   ts[i * 33 + bq + 2], ts[i * 33 + bq + 3]);
            *(float4*)&g_xT[(size_t)i * BATCH + B0 + bq] = w;
        }
    }
}

// One iteration's math for 4 f32x2 streams against one subnet's params.
// Params read phased (p0,p1 -> p2..p4 -> p5) to keep live ranges short.
__device__ __forceinline__ void kan_body(
    const ulonglong2* __restrict__ q,
    u64 xv0, u64 xv1, u64 xv2, u64 xv3,
    u64& A0, u64& A1, u64& A2, u64& A3)
{
    ulonglong2 p0 = q[0], p1 = q[1];
    u64 r10 = relu2(fma2(p0.x, xv0, p1.x));
    u64 r20 = relu2(fma2(p0.y, xv0, p1.y));
    u64 r11 = relu2(fma2(p0.x, xv1, p1.x));
    u64 r21 = relu2(fma2(p0.y, xv1, p1.y));
    u64 r12 = relu2(fma2(p0.x, xv2, p1.x));
    u64 r22 = relu2(fma2(p0.y, xv2, p1.y));
    u64 r13 = relu2(fma2(p0.x, xv3, p1.x));
    u64 r23 = relu2(fma2(p0.y, xv3, p1.y));
    ulonglong2 p2 = q[2], p3 = q[3], p4 = q[4];
    u64 ga0 = relu2(fma2(p2.x, r10, fma2(p2.y, r20, p4.x)));
    u64 gb0 = relu2(fma2(p3.x, r10, fma2(p3.y, r20, p4.y)));
    u64 ga1 = relu2(fma2(p2.x, r11, fma2(p2.y, r21, p4.x)));
    u64 gb1 = relu2(fma2(p3.x, r11, fma2(p3.y, r21, p4.y)));
    u64 ga2 = relu2(fma2(p2.x, r12, fma2(p2.y, r22, p4.x)));
    u64 gb2 = relu2(fma2(p3.x, r12, fma2(p3.y, r22, p4.y)));
    u64 ga3 = relu2(fma2(p2.x, r13, fma2(p2.y, r23, p4.x)));
    u64 gb3 = relu2(fma2(p3.x, r13, fma2(p3.y, r23, p4.y)));
    ulonglong2 p5 = q[5];
    A0 = fma2(p5.y, gb0, fma2(p5.x, ga0, A0));
    A1 = fma2(p5.y, gb1, fma2(p5.x, ga1, A1));
    A2 = fma2(p5.y, gb2, fma2(p5.x, ga2, A2));
    A3 = fma2(p5.y, gb3, fma2(p5.x, ga3, A3));
}

// One KAN layer (R6 shape + software-pipelined x loads). 256 threads = 8
// warps; warp ol owns output column o = o0+ol for a 256-batch strip; lane
// handles 4 f32x2 streams at b, b+64, b+128, b+192. Manual 2x unroll with
// alternating x-register buffers: each half prefetches the NEXT row's 4 xv
// (~76 issue slots ahead of use). Params: 48KB smem staged once, 6 uniform
// LDS.128 per (i,o), read phased.
// MODE 0: g_xT -> g_hT (transposed rows). MODE 1: g_hT -> dout [b][OUT].
template <int OUT, int MODE>
__global__ __launch_bounds__(256, 4) void kan_layer(float* __restrict__ dout)
{
    __shared__ float4 sp4[64 * 8 * 6];   // 48KB: [i][ol][6]

    int tid  = threadIdx.x;
    int lane = tid & 31;
    int ol   = tid >> 5;
    int o0   = blockIdx.y * 8;
    int o    = o0 + ol;
    int B0   = blockIdx.x * 256;
    int b    = B0 + lane * 2;

    // Stage params: per i, the 8 subnets n = i*OUT + o0..+7 are 48 contiguous
    // float4 in g_dup -> flat coalesced copy, 12 float4 per thread.
    const float4* dup = ((MODE == 0) ? g_dup0 : g_dup1);
#pragma unroll
    for (int s = tid; s < 3072; s += 256) {
        int i = s / 48;
        int r = s - i * 48;
        sp4[s] = dup[(size_t)(i * OUT + o0) * 6 + r];
    }

    float s3 = ((MODE == 0) ? g_b3s0 : g_b3s1)[o];
    __syncthreads();

    const float* src = (MODE == 0) ? g_xT : g_hT;
    const float* xr  = src + b;
    const ulonglong2* pb = ((const ulonglong2*)sp4) + ol * 6;

    u64 A0 = pk(s3, s3), A1 = A0, A2 = A0, A3 = A0;

    // Pipeline prologue: load row 0.
    u64 a0 = *(const u64*)(xr);
    u64 a1 = *(const u64*)(xr + 64);
    u64 a2 = *(const u64*)(xr + 128);
    u64 a3 = *(const u64*)(xr + 192);

#pragma unroll 1
    for (int i = 0; i < 64; i += 2) {
        const float* xn = xr + (size_t)(i + 1) * BATCH;
        // prefetch row i+1 into buffer B
        u64 c0 = *(const u64*)(xn);
        u64 c1 = *(const u64*)(xn + 64);
        u64 c2 = *(const u64*)(xn + 128);
        u64 c3 = *(const u64*)(xn + 192);
        kan_body(pb + (size_t)i * 48, a0, a1, a2, a3, A0, A1, A2, A3);
        // prefetch row i+2 into buffer A (row 64 at i=62 hits the pad row)
        const float* xn2 = xn + BATCH;
        a0 = *(const u64*)(xn2);
        a1 = *(const u64*)(xn2 + 64);
        a2 = *(const u64*)(xn2 + 128);
        a3 = *(const u64*)(xn2 + 192);
        kan_body(pb + (size_t)(i + 1) * 48, c0, c1, c2, c3, A0, A1, A2, A3);
    }

    if (MODE == 0) {
        float* row = g_hT + (size_t)o * BATCH + b;
        *(u64*)(row)       = A0;
        *(u64*)(row + 64)  = A1;
        *(u64*)(row + 128) = A2;
        *(u64*)(row + 192) = A3;
    } else {
        dout[(size_t)(b + 0)   * OUT + o] = flo(A0);
        dout[(size_t)(b + 1)   * OUT + o] = fhi(A0);
        dout[(size_t)(b + 64)  * OUT + o] = flo(A1);
        dout[(size_t)(b + 65)  * OUT + o] = fhi(A1);
        dout[(size_t)(b + 128) * OUT + o] = flo(A2);
        dout[(size_t)(b + 129) * OUT + o] = fhi(A2);
        dout[(size_t)(b + 192) * OUT + o] = flo(A3);
        dout[(size_t)(b + 193) * OUT + o] = fhi(A3);
    }
}

extern "C" void kernel_launch(void* const* d_in, const int* in_sizes, int n_in,
                              void* d_out, int out_size)
{
    const float* x    = (const float*)d_in[0];
    const float* l0W1 = (const float*)d_in[1];
    const float* l0b1 = (const float*)d_in[2];
    const float* l0W2 = (const float*)d_in[3];
    const float* l0b2 = (const float*)d_in[4];
    const float* l0W3 = (const float*)d_in[5];
    const float* l0b3 = (const float*)d_in[6];
    const float* l1W1 = (const float*)d_in[7];
    const float* l1b1 = (const float*)d_in[8];
    const float* l1W2 = (const float*)d_in[9];
    const float* l1b2 = (const float*)d_in[10];
    const float* l1W3 = (const float*)d_in[11];
    const float* l1b3 = (const float*)d_in[12];
    float* out = (float*)d_out;

    prep<<<542, 256>>>(x, l0W1, l0b1, l0W2, l0b2, l0W3, l0b3,
                          l1W1, l1b1, l1W2, l1b2, l1W3, l1b3);
    kan_layer<64, 0><<<dim3(BATCH / 256, 8), 256>>>(nullptr);  // 512 CTAs
    kan_layer<16, 1><<<dim3(BATCH / 256, 2), 256>>>(out);      // 128 CTAs
}